// round 1
// baseline (speedup 1.0000x reference)
#include <cuda_runtime.h>

#define BB 4
#define NN 2048
#define FF 128
#define DD 128
#define HH 4

#define LDX 132   // padded row stride (floats) for 128-wide tiles
#define LDA 68    // padded row stride (floats) for 64-wide tiles

// Scratch (allocation-free rule: __device__ globals)
__device__ float g_Xp[BB * NN * DD];            // 4 MB
__device__ float g_Yh[BB * HH * NN * DD];       // 16 MB

__device__ __forceinline__ float fast_tanh(float x) {
    // tanh(x) = (e^{2x}-1)/(e^{2x}+1); clamp so exp never overflows.
    x = fminf(15.0f, fmaxf(-15.0f, x));
    float e = __expf(2.0f * x);
    return __fdividef(e - 1.0f, e + 1.0f);
}

// ---------------------------------------------------------------------------
// Kernel 1: Xp = X @ W + bias ; Yh[h] = Xp @ attn[h]   (row-local, fused)
// grid = B*N/64 blocks, 256 threads. smem: X_s[64][LDX], W_s[128][LDX]
// ---------------------------------------------------------------------------
extern "C" __global__ void __launch_bounds__(256, 1)
k1_proj(const float* __restrict__ X, const float* __restrict__ Wk,
        const float* __restrict__ bias, const float* __restrict__ attn)
{
    extern __shared__ float sm[];
    float* X_s = sm;                // [64][LDX]
    float* W_s = sm + 64 * LDX;     // [128][LDX]

    const int tid  = threadIdx.x;
    const int row0 = blockIdx.x * 64;      // flattened b*N + n
    const int lane = tid & 31;             // -> 4 output cols at 4*lane
    const int warp = tid >> 5;             // -> 8 output rows at 8*warp

    // load X tile (64 x 128), coalesced float4
    #pragma unroll
    for (int k = 0; k < 8; k++) {
        int e = tid + k * 256;
        int r = e >> 5, c4 = (e & 31) * 4;
        *(float4*)(X_s + r * LDX + c4) =
            *(const float4*)(X + (size_t)(row0 + r) * FF + c4);
    }
    // load projection weights (128 x 128)
    #pragma unroll
    for (int k = 0; k < 16; k++) {
        int e = tid + k * 256;
        int r = e >> 5, c4 = (e & 31) * 4;
        *(float4*)(W_s + r * LDX + c4) = *(const float4*)(Wk + r * DD + c4);
    }
    __syncthreads();

    float4 bv = *(const float4*)(bias + lane * 4);
    float4 acc[8];
    #pragma unroll
    for (int r = 0; r < 8; r++) acc[r] = bv;

    #pragma unroll 4
    for (int f = 0; f < FF; f++) {
        float4 w = *(const float4*)(W_s + f * LDX + lane * 4);
        #pragma unroll
        for (int r = 0; r < 8; r++) {
            float a = X_s[(warp * 8 + r) * LDX + f];   // broadcast within warp
            acc[r].x += a * w.x; acc[r].y += a * w.y;
            acc[r].z += a * w.z; acc[r].w += a * w.w;
        }
    }
    __syncthreads();   // everyone done reading X_s / W_s

    // write Xp to smem (overwrite X_s) and to gmem
    #pragma unroll
    for (int r = 0; r < 8; r++) {
        int row = warp * 8 + r;
        *(float4*)(X_s + row * LDX + lane * 4) = acc[r];
        *(float4*)(g_Xp + (size_t)(row0 + row) * DD + lane * 4) = acc[r];
    }

    const int b = row0 >> 11;  // row0 / NN (blocks never straddle batches)

    for (int h = 0; h < HH; h++) {
        __syncthreads();   // Xp writes visible; previous W_s readers done
        #pragma unroll
        for (int k = 0; k < 16; k++) {
            int e = tid + k * 256;
            int r = e >> 5, c4 = (e & 31) * 4;
            *(float4*)(W_s + r * LDX + c4) =
                *(const float4*)(attn + h * DD * DD + r * DD + c4);
        }
        __syncthreads();

        float4 a2[8];
        #pragma unroll
        for (int r = 0; r < 8; r++) a2[r] = make_float4(0.f, 0.f, 0.f, 0.f);

        #pragma unroll 4
        for (int f = 0; f < DD; f++) {
            float4 w = *(const float4*)(W_s + f * LDX + lane * 4);
            #pragma unroll
            for (int r = 0; r < 8; r++) {
                float a = X_s[(warp * 8 + r) * LDX + f];
                a2[r].x += a * w.x; a2[r].y += a * w.y;
                a2[r].z += a * w.z; a2[r].w += a * w.w;
            }
        }
        #pragma unroll
        for (int r = 0; r < 8; r++) {
            int row = row0 + warp * 8 + r;
            int nn  = row & (NN - 1);
            *(float4*)(g_Yh + (size_t)((b * HH + h) * NN + nn) * DD + lane * 4) = a2[r];
        }
    }
}

// ---------------------------------------------------------------------------
// Kernel 2: fused  S = Yh_i @ Xp_m^T ; P = tanh(A*S) ; O += P @ Xp_m
// grid = (N/64, B), 256 threads.
// smem: Yh_s[4][64][LDX], Xp_s[64][LDX], A_s[64][LDA], P_s[64][LDA] (~199 KB)
// ---------------------------------------------------------------------------
extern "C" __global__ void __launch_bounds__(256, 1)
k2_main(const float* __restrict__ A, const float* __restrict__ X,
        float* __restrict__ out)
{
    extern __shared__ float sm[];
    float* Yh_s = sm;                          // 4 * 64*LDX
    float* Xp_s = sm + 4 * 64 * LDX;           // 64*LDX
    float* A_s  = Xp_s + 64 * LDX;             // 64*LDA
    float* P_s  = A_s + 64 * LDA;              // 64*LDA

    const int tid  = threadIdx.x;
    const int b    = blockIdx.y;
    const int i0   = blockIdx.x * 64;
    const int lane = tid & 31;   // GEMM2: cols 4*lane..+3
    const int warp = tid >> 5;   // GEMM2: rows 8*warp..+7
    const int tm   = tid & 15;   // GEMM1: m cols {tm, tm+16, tm+32, tm+48}
    const int ti   = tid >> 4;   // GEMM1: i rows 4*ti..+3

    // preload all 4 heads' Yh tiles for this i-tile
    for (int h = 0; h < HH; h++) {
        #pragma unroll
        for (int k = 0; k < 8; k++) {
            int e = tid + k * 256;
            int r = e >> 5, c4 = (e & 31) * 4;
            *(float4*)(Yh_s + h * 64 * LDX + r * LDX + c4) =
                *(const float4*)(g_Yh + (size_t)((b * HH + h) * NN + i0 + r) * DD + c4);
        }
    }

    float4 accO[8];
    #pragma unroll
    for (int r = 0; r < 8; r++) accO[r] = make_float4(0.f, 0.f, 0.f, 0.f);

    for (int mt = 0; mt < NN / 64; mt++) {
        __syncthreads();   // previous iteration's readers of Xp_s/A_s are done
        const int m0 = mt * 64;
        // Xp m-tile (64 x 128)
        #pragma unroll
        for (int k = 0; k < 8; k++) {
            int e = tid + k * 256;
            int r = e >> 5, c4 = (e & 31) * 4;
            *(float4*)(Xp_s + r * LDX + c4) =
                *(const float4*)(g_Xp + (size_t)(b * NN + m0 + r) * DD + c4);
        }
        // A tile (64 x 64)
        #pragma unroll
        for (int k = 0; k < 4; k++) {
            int e = tid + k * 256;
            int r = e >> 4, c4 = (e & 15) * 4;
            *(float4*)(A_s + r * LDA + c4) =
                *(const float4*)(A + (size_t)(b * NN + i0 + r) * NN + m0 + c4);
        }
        __syncthreads();

        for (int h = 0; h < HH; h++) {
            float s[4][4];
            #pragma unroll
            for (int r = 0; r < 4; r++)
                #pragma unroll
                for (int c = 0; c < 4; c++) s[r][c] = 0.f;

            const float* Yb = Yh_s + h * 64 * LDX + (ti * 4) * LDX;

            #pragma unroll 2
            for (int d = 0; d < DD; d += 4) {
                float4 av[4], bvv[4];
                #pragma unroll
                for (int r = 0; r < 4; r++)
                    av[r] = *(const float4*)(Yb + r * LDX + d);
                #pragma unroll
                for (int c = 0; c < 4; c++)
                    bvv[c] = *(const float4*)(Xp_s + (tm + 16 * c) * LDX + d);
                #pragma unroll
                for (int r = 0; r < 4; r++)
                    #pragma unroll
                    for (int c = 0; c < 4; c++)
                        s[r][c] += av[r].x * bvv[c].x + av[r].y * bvv[c].y
                                 + av[r].z * bvv[c].z + av[r].w * bvv[c].w;
            }

            // P = tanh(A * S), write to smem (conflict-free mapping)
            #pragma unroll
            for (int r = 0; r < 4; r++)
                #pragma unroll
                for (int c = 0; c < 4; c++) {
                    int i = ti * 4 + r, m = tm + 16 * c;
                    P_s[i * LDA + m] = fast_tanh(A_s[i * LDA + m] * s[r][c]);
                }
            __syncthreads();

            // O += P @ Xp_tile
            #pragma unroll 4
            for (int m = 0; m < 64; m++) {
                float4 xv = *(const float4*)(Xp_s + m * LDX + lane * 4);
                #pragma unroll
                for (int r = 0; r < 8; r++) {
                    float p = P_s[(warp * 8 + r) * LDA + m];   // broadcast
                    accO[r].x += p * xv.x; accO[r].y += p * xv.y;
                    accO[r].z += p * xv.z; accO[r].w += p * xv.w;
                }
            }
            __syncthreads();   // P_s reused next head
        }
    }

    // epilogue: mean over heads, relu, +X skip, relu
    #pragma unroll
    for (int r = 0; r < 8; r++) {
        int row = i0 + warp * 8 + r;
        float4 o = accO[r];
        o.x = fmaxf(o.x * 0.25f, 0.f); o.y = fmaxf(o.y * 0.25f, 0.f);
        o.z = fmaxf(o.z * 0.25f, 0.f); o.w = fmaxf(o.w * 0.25f, 0.f);
        float4 xv = *(const float4*)(X + (size_t)(b * NN + row) * FF + lane * 4);
        o.x = fmaxf(o.x + xv.x, 0.f); o.y = fmaxf(o.y + xv.y, 0.f);
        o.z = fmaxf(o.z + xv.z, 0.f); o.w = fmaxf(o.w + xv.w, 0.f);
        *(float4*)(out + (size_t)(b * NN + row) * DD + lane * 4) = o;
    }
}

// ---------------------------------------------------------------------------
extern "C" void kernel_launch(void* const* d_in, const int* in_sizes, int n_in,
                              void* d_out, int out_size)
{
    const float* X    = (const float*)d_in[0];   // [B,N,F]
    const float* A    = (const float*)d_in[1];   // [B,N,N]
    const float* Wk   = (const float*)d_in[2];   // [F,D]
    const float* bias = (const float*)d_in[3];   // [D]
    const float* attn = (const float*)d_in[4];   // [H,D,D]
    float* out = (float*)d_out;                  // [B,N,D]

    const size_t smem1 = (size_t)(64 * LDX + 128 * LDX) * sizeof(float);      // ~99 KB
    const size_t smem2 = (size_t)(4 * 64 * LDX + 64 * LDX + 2 * 64 * LDA)
                         * sizeof(float);                                     // ~199 KB
    cudaFuncSetAttribute(k1_proj, cudaFuncAttributeMaxDynamicSharedMemorySize, (int)smem1);
    cudaFuncSetAttribute(k2_main, cudaFuncAttributeMaxDynamicSharedMemorySize, (int)smem2);

    k1_proj<<<BB * NN / 64, 256, smem1>>>(X, Wk, bias, attn);
    k2_main<<<dim3(NN / 64, BB), 256, smem2>>>(A, X, out);
}

// round 4
// speedup vs baseline: 1.6088x; 1.6088x over previous
#include <cuda_runtime.h>
#include <cuda_bf16.h>
#include <cstdint>

#define BB 4
#define NN 2048
#define FF 128
#define DD 128
#define HH 4

#define LDX 132   // fp32 smem stride (k1)
#define LDH 136   // bf16 elem stride, 128-wide tiles (272B rows: 16B-aligned, odd*16 -> conflict-free)
#define LDP2 72   // bf16 elem stride, 64-wide P tiles (144B rows)
#define LDA 68    // fp32 stride for 64-wide A tiles

// Scratch (__device__ globals: allocation-free rule)
__device__ __nv_bfloat16 g_XpH[BB * NN * DD];        // 2 MB
__device__ __nv_bfloat16 g_XpL[BB * NN * DD];        // 2 MB
__device__ __nv_bfloat16 g_YhH[BB * HH * NN * DD];   // 8 MB
__device__ __nv_bfloat16 g_YhL[BB * HH * NN * DD];   // 8 MB

// ---------------- helpers ----------------
__device__ __forceinline__ void ldsm4(unsigned* r, unsigned a) {
    asm volatile("ldmatrix.sync.aligned.m8n8.x4.shared.b16 {%0,%1,%2,%3},[%4];"
                 : "=r"(r[0]), "=r"(r[1]), "=r"(r[2]), "=r"(r[3]) : "r"(a));
}
__device__ __forceinline__ void ldsm4t(unsigned* r, unsigned a) {
    asm volatile("ldmatrix.sync.aligned.m8n8.x4.trans.shared.b16 {%0,%1,%2,%3},[%4];"
                 : "=r"(r[0]), "=r"(r[1]), "=r"(r[2]), "=r"(r[3]) : "r"(a));
}
__device__ __forceinline__ void mma_bf16(float* c, const unsigned* a, const unsigned* b) {
    asm volatile("mma.sync.aligned.m16n8k16.row.col.f32.bf16.bf16.f32 "
                 "{%0,%1,%2,%3},{%4,%5,%6,%7},{%8,%9},{%0,%1,%2,%3};"
                 : "+f"(c[0]), "+f"(c[1]), "+f"(c[2]), "+f"(c[3])
                 : "r"(a[0]), "r"(a[1]), "r"(a[2]), "r"(a[3]), "r"(b[0]), "r"(b[1]));
}

// proven-accurate tanh (R1: rel_err 2.6e-6): 2 MUFU + few FMA
__device__ __forceinline__ float fast_tanh(float x) {
    x = fminf(15.0f, fmaxf(-15.0f, x));
    float e = __expf(2.0f * x);
    return __fdividef(e - 1.0f, e + 1.0f);
}

// split fp32 pair -> bf16 hi pair + bf16 lo pair, store packed
__device__ __forceinline__ void split_st2(float a, float b,
                                          __nv_bfloat16* ph, __nv_bfloat16* pl) {
    __nv_bfloat16 ha = __float2bfloat16(a), hb = __float2bfloat16(b);
    __nv_bfloat162 hv; hv.x = ha; hv.y = hb;
    __nv_bfloat162 lv;
    lv.x = __float2bfloat16(a - __bfloat162float(ha));
    lv.y = __float2bfloat16(b - __bfloat162float(hb));
    *reinterpret_cast<__nv_bfloat162*>(ph) = hv;
    *reinterpret_cast<__nv_bfloat162*>(pl) = lv;
}

// ---------------------------------------------------------------------------
// Kernel 1: Xp = X @ W + bias ; Yh[h] = Xp @ attn[h]; outputs split to bf16 hi/lo
// ---------------------------------------------------------------------------
extern "C" __global__ void __launch_bounds__(256, 1)
k1_proj(const float* __restrict__ X, const float* __restrict__ Wk,
        const float* __restrict__ bias, const float* __restrict__ attn)
{
    extern __shared__ float sm[];
    float* X_s = sm;                // [64][LDX]
    float* W_s = sm + 64 * LDX;     // [128][LDX]

    const int tid  = threadIdx.x;
    const int row0 = blockIdx.x * 64;
    const int lane = tid & 31;
    const int warp = tid >> 5;

    #pragma unroll
    for (int k = 0; k < 8; k++) {
        int e = tid + k * 256;
        int r = e >> 5, c4 = (e & 31) * 4;
        *(float4*)(X_s + r * LDX + c4) =
            *(const float4*)(X + (size_t)(row0 + r) * FF + c4);
    }
    #pragma unroll
    for (int k = 0; k < 16; k++) {
        int e = tid + k * 256;
        int r = e >> 5, c4 = (e & 31) * 4;
        *(float4*)(W_s + r * LDX + c4) = *(const float4*)(Wk + r * DD + c4);
    }
    __syncthreads();

    float4 bv = *(const float4*)(bias + lane * 4);
    float4 acc[8];
    #pragma unroll
    for (int r = 0; r < 8; r++) acc[r] = bv;

    #pragma unroll 4
    for (int f = 0; f < FF; f++) {
        float4 w = *(const float4*)(W_s + f * LDX + lane * 4);
        #pragma unroll
        for (int r = 0; r < 8; r++) {
            float a = X_s[(warp * 8 + r) * LDX + f];
            acc[r].x += a * w.x; acc[r].y += a * w.y;
            acc[r].z += a * w.z; acc[r].w += a * w.w;
        }
    }
    __syncthreads();

    #pragma unroll
    for (int r = 0; r < 8; r++) {
        int row = warp * 8 + r;
        *(float4*)(X_s + row * LDX + lane * 4) = acc[r];
        size_t g = (size_t)(row0 + row) * DD + lane * 4;
        split_st2(acc[r].x, acc[r].y, g_XpH + g,     g_XpL + g);
        split_st2(acc[r].z, acc[r].w, g_XpH + g + 2, g_XpL + g + 2);
    }

    const int b = row0 >> 11;

    for (int h = 0; h < HH; h++) {
        __syncthreads();
        #pragma unroll
        for (int k = 0; k < 16; k++) {
            int e = tid + k * 256;
            int r = e >> 5, c4 = (e & 31) * 4;
            *(float4*)(W_s + r * LDX + c4) =
                *(const float4*)(attn + h * DD * DD + r * DD + c4);
        }
        __syncthreads();

        float4 a2[8];
        #pragma unroll
        for (int r = 0; r < 8; r++) a2[r] = make_float4(0.f, 0.f, 0.f, 0.f);

        #pragma unroll 4
        for (int f = 0; f < DD; f++) {
            float4 w = *(const float4*)(W_s + f * LDX + lane * 4);
            #pragma unroll
            for (int r = 0; r < 8; r++) {
                float a = X_s[(warp * 8 + r) * LDX + f];
                a2[r].x += a * w.x; a2[r].y += a * w.y;
                a2[r].z += a * w.z; a2[r].w += a * w.w;
            }
        }
        #pragma unroll
        for (int r = 0; r < 8; r++) {
            int nn = (row0 + warp * 8 + r) & (NN - 1);
            size_t g = (size_t)((b * HH + h) * NN + nn) * DD + lane * 4;
            split_st2(a2[r].x, a2[r].y, g_YhH + g,     g_YhL + g);
            split_st2(a2[r].z, a2[r].w, g_YhH + g + 2, g_YhL + g + 2);
        }
    }
}

// ---------------------------------------------------------------------------
// Kernel 2: bf16-split tensor-core flash loop.
//   per (b, 64-row i-tile): for h: cache Yh a-frags; for mt:
//     S = Yh_i @ Xp_m^T (3-term bf16 mma), P = tanh(A*S) -> split bf16,
//     O += P @ Xp_m (3-term bf16 mma). Epilogue mean/relu/skip/relu.
// ---------------------------------------------------------------------------
extern "C" __global__ void __launch_bounds__(256, 1)
k2_main(const float* __restrict__ A, const float* __restrict__ X,
        float* __restrict__ out)
{
    extern __shared__ char sb[];
    __nv_bfloat16* XpH_s = (__nv_bfloat16*)(sb);            // 64*LDH*2 = 17408 B
    __nv_bfloat16* XpL_s = (__nv_bfloat16*)(sb + 17408);
    float*         A_s   = (float*)(sb + 34816);            // 64*LDA*4 = 17408 B
    __nv_bfloat16* PH_s  = (__nv_bfloat16*)(sb + 52224);    // 64*LDP2*2 = 9216 B
    __nv_bfloat16* PL_s  = (__nv_bfloat16*)(sb + 61440);

    const int tid = threadIdx.x;
    const int w   = tid >> 5;
    const int l   = tid & 31;
    const int b   = blockIdx.y;
    const int i0  = blockIdx.x * 64;

    const unsigned xh_b = (unsigned)__cvta_generic_to_shared(XpH_s);
    const unsigned xl_b = (unsigned)__cvta_generic_to_shared(XpL_s);
    const unsigned ph_b = (unsigned)__cvta_generic_to_shared(PH_s);
    const unsigned pl_b = (unsigned)__cvta_generic_to_shared(PL_s);

    // GEMM1 warp tile: S rows r1..+16, cols c1..+32 (4x2 warps)
    const int r1 = 16 * (w & 3), c1 = 32 * (w >> 2);
    // GEMM2 warp tile: O rows r2..+32, cols c2..+32 (2x4 warps)
    const int r2 = 32 * (w & 1), c2 = 32 * (w >> 1);

    const int lq = l >> 2, lr = l & 3;

    // ldmatrix lane offsets (in b16 elements)
    const int a_row = (l & 7) + 8 * ((l >> 3) & 1);  // A-type x4 / trans-B x4
    const int a_col = 8 * (l >> 4);
    const int b1_row = (l & 7) + 8 * (l >> 4);       // GEMM1 B x4
    const int b1_col = 8 * ((l >> 3) & 1);

    float O[2][4][4];
    #pragma unroll
    for (int m2 = 0; m2 < 2; m2++)
        #pragma unroll
        for (int nt = 0; nt < 4; nt++)
            #pragma unroll
            for (int k = 0; k < 4; k++) O[m2][nt][k] = 0.f;

    for (int h = 0; h < HH; h++) {
        // ---- stage this head's Yh i-tile (hi/lo) into Xp smem, cache a-frags ----
        __syncthreads();
        {
            const __nv_bfloat16* gH = g_YhH + ((size_t)(b * HH + h) * NN + i0) * DD;
            const __nv_bfloat16* gL = g_YhL + ((size_t)(b * HH + h) * NN + i0) * DD;
            #pragma unroll
            for (int k = 0; k < 4; k++) {
                int e = tid + k * 256;
                int r = e >> 4, c = (e & 15) * 8;
                *(uint4*)(XpH_s + r * LDH + c) = *(const uint4*)(gH + r * DD + c);
                *(uint4*)(XpL_s + r * LDH + c) = *(const uint4*)(gL + r * DD + c);
            }
        }
        __syncthreads();

        unsigned yhh[8][4], yhl[8][4];
        #pragma unroll
        for (int ks = 0; ks < 8; ks++) {
            unsigned off = (unsigned)(((r1 + a_row) * LDH + ks * 16 + a_col) * 2);
            ldsm4(yhh[ks], xh_b + off);
            ldsm4(yhl[ks], xl_b + off);
        }

        for (int mt = 0; mt < NN / 64; mt++) {
            __syncthreads();
            const int m0 = mt * 64;
            // fill Xp m-tile (hi/lo) + A tile
            {
                const __nv_bfloat16* gH = g_XpH + ((size_t)b * NN + m0) * DD;
                const __nv_bfloat16* gL = g_XpL + ((size_t)b * NN + m0) * DD;
                #pragma unroll
                for (int k = 0; k < 4; k++) {
                    int e = tid + k * 256;
                    int r = e >> 4, c = (e & 15) * 8;
                    *(uint4*)(XpH_s + r * LDH + c) = *(const uint4*)(gH + r * DD + c);
                    *(uint4*)(XpL_s + r * LDH + c) = *(const uint4*)(gL + r * DD + c);
                }
                #pragma unroll
                for (int k = 0; k < 4; k++) {
                    int e = tid + k * 256;
                    int r = e >> 4, c4 = (e & 15) * 4;
                    *(float4*)(A_s + r * LDA + c4) =
                        *(const float4*)(A + ((size_t)b * NN + i0 + r) * NN + m0 + c4);
                }
            }
            __syncthreads();

            // ---- GEMM1: S[16x32] = Yh @ Xp^T, 3-term bf16 split ----
            float S[4][4];
            #pragma unroll
            for (int nt = 0; nt < 4; nt++)
                #pragma unroll
                for (int k = 0; k < 4; k++) S[nt][k] = 0.f;

            #pragma unroll
            for (int ks = 0; ks < 8; ks++) {
                #pragma unroll
                for (int ntp = 0; ntp < 2; ntp++) {
                    unsigned bh[4], bl[4];
                    unsigned off = (unsigned)(((c1 + 16 * ntp + b1_row) * LDH
                                               + ks * 16 + b1_col) * 2);
                    ldsm4(bh, xh_b + off);
                    ldsm4(bl, xl_b + off);
                    mma_bf16(S[2 * ntp],     yhh[ks], &bh[0]);
                    mma_bf16(S[2 * ntp],     yhh[ks], &bl[0]);
                    mma_bf16(S[2 * ntp],     yhl[ks], &bh[0]);
                    mma_bf16(S[2 * ntp + 1], yhh[ks], &bh[2]);
                    mma_bf16(S[2 * ntp + 1], yhh[ks], &bl[2]);
                    mma_bf16(S[2 * ntp + 1], yhl[ks], &bh[2]);
                }
            }

            // ---- P = tanh(A*S) -> split bf16, store ----
            #pragma unroll
            for (int nt = 0; nt < 4; nt++) {
                int mcol = c1 + 8 * nt + 2 * lr;
                int irow = r1 + lq;
                float2 a01 = *(const float2*)(A_s + irow * LDA + mcol);
                float2 a23 = *(const float2*)(A_s + (irow + 8) * LDA + mcol);
                float p0 = fast_tanh(a01.x * S[nt][0]);
                float p1 = fast_tanh(a01.y * S[nt][1]);
                float p2 = fast_tanh(a23.x * S[nt][2]);
                float p3 = fast_tanh(a23.y * S[nt][3]);
                split_st2(p0, p1, PH_s + irow * LDP2 + mcol,       PL_s + irow * LDP2 + mcol);
                split_st2(p2, p3, PH_s + (irow + 8) * LDP2 + mcol, PL_s + (irow + 8) * LDP2 + mcol);
            }
            __syncthreads();

            // ---- GEMM2: O[32x32] += P @ Xp, 3-term bf16 split ----
            #pragma unroll
            for (int ks = 0; ks < 4; ks++) {
                unsigned ah[2][4], al[2][4];
                #pragma unroll
                for (int m2 = 0; m2 < 2; m2++) {
                    unsigned off = (unsigned)(((r2 + 16 * m2 + a_row) * LDP2
                                               + ks * 16 + a_col) * 2);
                    ldsm4(ah[m2], ph_b + off);
                    ldsm4(al[m2], pl_b + off);
                }
                #pragma unroll
                for (int ntp = 0; ntp < 2; ntp++) {
                    unsigned bh[4], bl[4];
                    unsigned off = (unsigned)(((ks * 16 + a_row) * LDH
                                               + c2 + 16 * ntp + a_col) * 2);
                    ldsm4t(bh, xh_b + off);
                    ldsm4t(bl, xl_b + off);
                    #pragma unroll
                    for (int m2 = 0; m2 < 2; m2++) {
                        mma_bf16(O[m2][2 * ntp],     ah[m2], &bh[0]);
                        mma_bf16(O[m2][2 * ntp],     ah[m2], &bl[0]);
                        mma_bf16(O[m2][2 * ntp],     al[m2], &bh[0]);
                        mma_bf16(O[m2][2 * ntp + 1], ah[m2], &bh[2]);
                        mma_bf16(O[m2][2 * ntp + 1], ah[m2], &bl[2]);
                        mma_bf16(O[m2][2 * ntp + 1], al[m2], &bh[2]);
                    }
                }
            }
        }
    }

    // ---- epilogue: mean over heads, relu, +X, relu ----
    #pragma unroll
    for (int m2 = 0; m2 < 2; m2++) {
        #pragma unroll
        for (int nt = 0; nt < 4; nt++) {
            int gr = i0 + r2 + 16 * m2 + lq;
            int gc = c2 + 8 * nt + 2 * lr;

            float2 v0 = make_float2(O[m2][nt][0], O[m2][nt][1]);
            float2 v1 = make_float2(O[m2][nt][2], O[m2][nt][3]);

            float2 x0 = *(const float2*)(X + ((size_t)b * NN + gr) * FF + gc);
            float2 x1 = *(const float2*)(X + ((size_t)b * NN + gr + 8) * FF + gc);

            v0.x = fmaxf(fmaxf(v0.x * 0.25f, 0.f) + x0.x, 0.f);
            v0.y = fmaxf(fmaxf(v0.y * 0.25f, 0.f) + x0.y, 0.f);
            v1.x = fmaxf(fmaxf(v1.x * 0.25f, 0.f) + x1.x, 0.f);
            v1.y = fmaxf(fmaxf(v1.y * 0.25f, 0.f) + x1.y, 0.f);

            *(float2*)(out + ((size_t)b * NN + gr) * DD + gc) = v0;
            *(float2*)(out + ((size_t)b * NN + gr + 8) * DD + gc) = v1;
        }
    }
}

// ---------------------------------------------------------------------------
extern "C" void kernel_launch(void* const* d_in, const int* in_sizes, int n_in,
                              void* d_out, int out_size)
{
    const float* X    = (const float*)d_in[0];   // [B,N,F]
    const float* A    = (const float*)d_in[1];   // [B,N,N]
    const float* Wk   = (const float*)d_in[2];   // [F,D]
    const float* bias = (const float*)d_in[3];   // [D]
    const float* attn = (const float*)d_in[4];   // [H,D,D]
    float* out = (float*)d_out;                  // [B,N,D]

    const size_t smem1 = (size_t)(64 * LDX + 128 * LDX) * sizeof(float);
    const size_t smem2 = 70656;
    cudaFuncSetAttribute(k1_proj, cudaFuncAttributeMaxDynamicSharedMemorySize, (int)smem1);
    cudaFuncSetAttribute(k2_main, cudaFuncAttributeMaxDynamicSharedMemorySize, (int)smem2);

    k1_proj<<<BB * NN / 64, 256, smem1>>>(X, Wk, bias, attn);
    k2_main<<<dim3(NN / 64, BB), 256, smem2>>>(A, X, out);
}

// round 9
// speedup vs baseline: 3.1476x; 1.9565x over previous
#include <cuda_runtime.h>
#include <cuda_fp16.h>
#include <cstdint>

#define BB 4
#define NN 2048
#define FF 128
#define DD 128
#define HH 4

#define LDX 132   // fp32 smem stride (k1)
#define LDH 136   // half elem stride for 128-wide tiles (272B rows, 16B aligned, conflict-free)
#define LDA 68    // fp32 stride for 64-wide A tiles

// Scratch (__device__ globals: allocation-free rule)
__device__ __half g_XpH[BB * NN * DD];          // 2 MB
__device__ __half g_XpL[BB * NN * DD];          // 2 MB
__device__ __half g_YhH[BB * HH * NN * DD];     // 8 MB
__device__ __half g_YhL[BB * HH * NN * DD];     // 8 MB
__device__ float  g_Opart[2 * BB * NN * DD];    // 8 MB (per-head-pair partials)

// ---------------- helpers ----------------
__device__ __forceinline__ void ldsm4(unsigned* r, unsigned a) {
    asm volatile("ldmatrix.sync.aligned.m8n8.x4.shared.b16 {%0,%1,%2,%3},[%4];"
                 : "=r"(r[0]), "=r"(r[1]), "=r"(r[2]), "=r"(r[3]) : "r"(a));
}
__device__ __forceinline__ void ldsm4t(unsigned* r, unsigned a) {
    asm volatile("ldmatrix.sync.aligned.m8n8.x4.trans.shared.b16 {%0,%1,%2,%3},[%4];"
                 : "=r"(r[0]), "=r"(r[1]), "=r"(r[2]), "=r"(r[3]) : "r"(a));
}
__device__ __forceinline__ void mma_f16(float* c, const unsigned* a, const unsigned* b) {
    asm volatile("mma.sync.aligned.m16n8k16.row.col.f32.f16.f16.f32 "
                 "{%0,%1,%2,%3},{%4,%5,%6,%7},{%8,%9},{%0,%1,%2,%3};"
                 : "+f"(c[0]), "+f"(c[1]), "+f"(c[2]), "+f"(c[3])
                 : "r"(a[0]), "r"(a[1]), "r"(a[2]), "r"(a[3]), "r"(b[0]), "r"(b[1]));
}

__device__ __forceinline__ float fast_tanh(float x) {
    x = fminf(15.0f, fmaxf(-15.0f, x));
    float e = __expf(2.0f * x);
    return __fdividef(e - 1.0f, e + 1.0f);
}

// fp32 pair -> fp16 hi pair + fp16 lo pair (2-way split), packed stores
__device__ __forceinline__ void split_st2h(float a, float b, __half* ph, __half* pl) {
    __half ha = __float2half_rn(a), hb = __float2half_rn(b);
    __half2 hv; hv.x = ha; hv.y = hb;
    __half2 lv;
    lv.x = __float2half_rn(a - __half2float(ha));
    lv.y = __float2half_rn(b - __half2float(hb));
    *reinterpret_cast<__half2*>(ph) = hv;
    *reinterpret_cast<__half2*>(pl) = lv;
}

// ---------------------------------------------------------------------------
// Kernel 1: Xp = X @ W + bias (split fp16) ; Yh[h] = Xp @ attn[h] (split fp16)
// ---------------------------------------------------------------------------
extern "C" __global__ void __launch_bounds__(256, 1)
k1_proj(const float* __restrict__ X, const float* __restrict__ Wk,
        const float* __restrict__ bias, const float* __restrict__ attn)
{
    extern __shared__ float sm[];
    float* X_s = sm;                // [64][LDX]
    float* W_s = sm + 64 * LDX;     // [128][LDX]

    const int tid  = threadIdx.x;
    const int row0 = blockIdx.x * 64;
    const int lane = tid & 31;
    const int warp = tid >> 5;

    #pragma unroll
    for (int k = 0; k < 8; k++) {
        int e = tid + k * 256;
        int r = e >> 5, c4 = (e & 31) * 4;
        *(float4*)(X_s + r * LDX + c4) =
            *(const float4*)(X + (size_t)(row0 + r) * FF + c4);
    }
    #pragma unroll
    for (int k = 0; k < 16; k++) {
        int e = tid + k * 256;
        int r = e >> 5, c4 = (e & 31) * 4;
        *(float4*)(W_s + r * LDX + c4) = *(const float4*)(Wk + r * DD + c4);
    }
    __syncthreads();

    float4 bv = *(const float4*)(bias + lane * 4);
    float4 acc[8];
    #pragma unroll
    for (int r = 0; r < 8; r++) acc[r] = bv;

    #pragma unroll 4
    for (int f = 0; f < FF; f++) {
        float4 w = *(const float4*)(W_s + f * LDX + lane * 4);
        #pragma unroll
        for (int r = 0; r < 8; r++) {
            float a = X_s[(warp * 8 + r) * LDX + f];
            acc[r].x += a * w.x; acc[r].y += a * w.y;
            acc[r].z += a * w.z; acc[r].w += a * w.w;
        }
    }
    __syncthreads();

    #pragma unroll
    for (int r = 0; r < 8; r++) {
        int row = warp * 8 + r;
        *(float4*)(X_s + row * LDX + lane * 4) = acc[r];
        size_t g = (size_t)(row0 + row) * DD + lane * 4;
        split_st2h(acc[r].x, acc[r].y, g_XpH + g,     g_XpL + g);
        split_st2h(acc[r].z, acc[r].w, g_XpH + g + 2, g_XpL + g + 2);
    }

    const int b = row0 >> 11;

    for (int h = 0; h < HH; h++) {
        __syncthreads();
        #pragma unroll
        for (int k = 0; k < 16; k++) {
            int e = tid + k * 256;
            int r = e >> 5, c4 = (e & 31) * 4;
            *(float4*)(W_s + r * LDX + c4) =
                *(const float4*)(attn + h * DD * DD + r * DD + c4);
        }
        __syncthreads();

        float4 a2[8];
        #pragma unroll
        for (int r = 0; r < 8; r++) a2[r] = make_float4(0.f, 0.f, 0.f, 0.f);

        #pragma unroll 4
        for (int f = 0; f < DD; f++) {
            float4 w = *(const float4*)(W_s + f * LDX + lane * 4);
            #pragma unroll
            for (int r = 0; r < 8; r++) {
                float a = X_s[(warp * 8 + r) * LDX + f];
                a2[r].x += a * w.x; a2[r].y += a * w.y;
                a2[r].z += a * w.z; a2[r].w += a * w.w;
            }
        }
        #pragma unroll
        for (int r = 0; r < 8; r++) {
            int nn = (row0 + warp * 8 + r) & (NN - 1);
            size_t g = (size_t)((b * HH + h) * NN + nn) * DD + lane * 4;
            split_st2h(a2[r].x, a2[r].y, g_YhH + g,     g_YhL + g);
            split_st2h(a2[r].z, a2[r].w, g_YhH + g + 2, g_YhL + g + 2);
        }
    }
}

// ---------------------------------------------------------------------------
// Kernel 2: 64-thread CTAs (2 warps), 32-row i-tile, 2 heads per CTA.
// GEMM1 (3-term): S = YhH@XpH^T + YhH@XpL^T + YhL@XpH^T
// P = tanh(A*S) packed IN REGISTERS as GEMM2 A-frags (single fp16)
// GEMM2 (2-term): Opart += P@XpH + P@XpL.  grid = (N/32, B, 2).
// ---------------------------------------------------------------------------
extern "C" __global__ void __launch_bounds__(64, 4)
k2_main(const float* __restrict__ A)
{
    extern __shared__ char sb[];
    __half* XpH_s = (__half*)(sb);            // [64][LDH] = 17408 B
    __half* XpL_s = (__half*)(sb + 17408);    // [64][LDH]
    float*  A_s   = (float*)(sb + 34816);     // [32][LDA] = 8704 B

    const int tid = threadIdx.x;
    const int w   = tid >> 5;                 // 0..1
    const int l   = tid & 31;
    const int b   = blockIdx.y;
    const int i0  = blockIdx.x * 32;
    const int hp  = blockIdx.z;               // head pair

    const unsigned xh_b = (unsigned)__cvta_generic_to_shared(XpH_s);
    const unsigned xl_b = (unsigned)__cvta_generic_to_shared(XpL_s);

    const int r1 = 16 * w;                    // warp's i-rows within tile
    const int lq = l >> 2, lr = l & 3;

    const int a_row = (l & 7) + 8 * ((l >> 3) & 1);  // A-type / trans-B lane rows
    const int a_col = 8 * (l >> 4);
    const int b1_row = (l & 7) + 8 * (l >> 4);       // non-trans B lane rows
    const int b1_col = 8 * ((l >> 3) & 1);

    float O[16][4];
    #pragma unroll
    for (int f = 0; f < 16; f++)
        #pragma unroll
        for (int k = 0; k < 4; k++) O[f][k] = 0.f;

    for (int hh = 0; hh < 2; hh++) {
        const int h = hp * 2 + hh;
        __syncthreads();   // prev iter finished reading XpH_s/XpL_s
        // stage Yh i-tile (32x128, hi->XpH_s rows, lo->XpL_s rows)
        {
            const __half* YgH = g_YhH + ((size_t)(b * HH + h) * NN + i0) * DD;
            const __half* YgL = g_YhL + ((size_t)(b * HH + h) * NN + i0) * DD;
            #pragma unroll
            for (int k = 0; k < 8; k++) {
                int e = tid + k * 64;
                int r = e >> 4, c8 = (e & 15) * 8;
                *(uint4*)(XpH_s + r * LDH + c8) = *(const uint4*)(YgH + r * DD + c8);
                *(uint4*)(XpL_s + r * LDH + c8) = *(const uint4*)(YgL + r * DD + c8);
            }
        }
        __syncthreads();
        unsigned yhh[8][4], yhl[8][4];
        #pragma unroll
        for (int ks = 0; ks < 8; ks++) {
            unsigned off = (unsigned)(((r1 + a_row) * LDH + 16 * ks + a_col) * 2);
            ldsm4(yhh[ks], xh_b + off);
            ldsm4(yhl[ks], xl_b + off);
        }

        for (int mt = 0; mt < NN / 64; mt++) {
            __syncthreads();  // yh ldsm done (mt=0) / prev GEMM reads done
            const int m0 = mt * 64;
            {
                const __half* gH = g_XpH + ((size_t)b * NN + m0) * DD;
                const __half* gL = g_XpL + ((size_t)b * NN + m0) * DD;
                #pragma unroll
                for (int k = 0; k < 16; k++) {
                    int e = tid + k * 64;
                    int r = e >> 4, c8 = (e & 15) * 8;
                    *(uint4*)(XpH_s + r * LDH + c8) = *(const uint4*)(gH + r * DD + c8);
                    *(uint4*)(XpL_s + r * LDH + c8) = *(const uint4*)(gL + r * DD + c8);
                }
                #pragma unroll
                for (int k = 0; k < 8; k++) {
                    int e = tid + k * 64;
                    int r = e >> 4, c4 = (e & 15) * 4;
                    *(float4*)(A_s + r * LDA + c4) =
                        *(const float4*)(A + ((size_t)b * NN + i0 + r) * NN + m0 + c4);
                }
            }
            __syncthreads();

            // ---- GEMM1 (3-term): S[16 x 64] ----
            float S[8][4];
            #pragma unroll
            for (int f = 0; f < 8; f++)
                #pragma unroll
                for (int k = 0; k < 4; k++) S[f][k] = 0.f;

            #pragma unroll
            for (int ks = 0; ks < 8; ks++) {
                #pragma unroll
                for (int ng = 0; ng < 4; ng++) {
                    unsigned bh[4], bl[4];
                    unsigned off = (unsigned)(((16 * ng + b1_row) * LDH + 16 * ks + b1_col) * 2);
                    ldsm4(bh, xh_b + off);
                    ldsm4(bl, xl_b + off);
                    mma_f16(S[2 * ng],     yhh[ks], &bh[0]);
                    mma_f16(S[2 * ng],     yhh[ks], &bl[0]);
                    mma_f16(S[2 * ng],     yhl[ks], &bh[0]);
                    mma_f16(S[2 * ng + 1], yhh[ks], &bh[2]);
                    mma_f16(S[2 * ng + 1], yhh[ks], &bl[2]);
                    mma_f16(S[2 * ng + 1], yhl[ks], &bh[2]);
                }
            }

            // ---- P = tanh(A*S): pack directly into GEMM2 A-fragments ----
            unsigned pa[4][4];
            #pragma unroll
            for (int nf = 0; nf < 8; nf++) {
                int row = r1 + lq, col = 8 * nf + 2 * lr;
                float2 a01 = *(const float2*)(A_s + row * LDA + col);
                float2 a23 = *(const float2*)(A_s + (row + 8) * LDA + col);
                float p0 = fast_tanh(a01.x * S[nf][0]);
                float p1 = fast_tanh(a01.y * S[nf][1]);
                float p2 = fast_tanh(a23.x * S[nf][2]);
                float p3 = fast_tanh(a23.y * S[nf][3]);
                __half2 h01; h01.x = __float2half_rn(p0); h01.y = __float2half_rn(p1);
                __half2 h23; h23.x = __float2half_rn(p2); h23.y = __float2half_rn(p3);
                pa[nf >> 1][(nf & 1) * 2 + 0] = *reinterpret_cast<unsigned*>(&h01);
                pa[nf >> 1][(nf & 1) * 2 + 1] = *reinterpret_cast<unsigned*>(&h23);
            }

            // ---- GEMM2 (2-term): O[16 x 128] += P @ (XpH + XpL) ----
            #pragma unroll
            for (int ks2 = 0; ks2 < 4; ks2++) {
                #pragma unroll
                for (int ng = 0; ng < 8; ng++) {
                    unsigned bh[4], bl[4];
                    unsigned off = (unsigned)(((16 * ks2 + a_row) * LDH + 16 * ng + a_col) * 2);
                    ldsm4t(bh, xh_b + off);
                    ldsm4t(bl, xl_b + off);
                    mma_f16(O[2 * ng],     pa[ks2], &bh[0]);
                    mma_f16(O[2 * ng],     pa[ks2], &bl[0]);
                    mma_f16(O[2 * ng + 1], pa[ks2], &bh[2]);
                    mma_f16(O[2 * ng + 1], pa[ks2], &bl[2]);
                }
            }
        }
    }

    // ---- write fp32 partial (sum over this CTA's 2 heads) ----
    {
        float* Op = g_Opart + ((size_t)(hp * BB + b) * NN + i0 + r1 + lq) * DD;
        #pragma unroll
        for (int f = 0; f < 16; f++) {
            *(float2*)(Op + 8 * f + 2 * lr)            = make_float2(O[f][0], O[f][1]);
            *(float2*)(Op + 8 * DD + 8 * f + 2 * lr)   = make_float2(O[f][2], O[f][3]);
        }
    }
}

// ---------------------------------------------------------------------------
// Kernel 3: combine partials + epilogue: relu(relu((P0+P1)/4) + X)
// ---------------------------------------------------------------------------
extern "C" __global__ void __launch_bounds__(256, 4)
k3_combine(const float* __restrict__ X, float* __restrict__ out)
{
    int idx = blockIdx.x * 256 + threadIdx.x;   // float4 index
    const float4* p0 = (const float4*)g_Opart;
    const float4* p1 = (const float4*)(g_Opart + (size_t)BB * NN * DD);
    float4 a = p0[idx], b = p1[idx];
    float4 x = ((const float4*)X)[idx];
    float4 o;
    o.x = fmaxf(fmaxf((a.x + b.x) * 0.25f, 0.f) + x.x, 0.f);
    o.y = fmaxf(fmaxf((a.y + b.y) * 0.25f, 0.f) + x.y, 0.f);
    o.z = fmaxf(fmaxf((a.z + b.z) * 0.25f, 0.f) + x.z, 0.f);
    o.w = fmaxf(fmaxf((a.w + b.w) * 0.25f, 0.f) + x.w, 0.f);
    ((float4*)out)[idx] = o;
}

// ---------------------------------------------------------------------------
extern "C" void kernel_launch(void* const* d_in, const int* in_sizes, int n_in,
                              void* d_out, int out_size)
{
    const float* X    = (const float*)d_in[0];   // [B,N,F]
    const float* A    = (const float*)d_in[1];   // [B,N,N]
    const float* Wk   = (const float*)d_in[2];   // [F,D]
    const float* bias = (const float*)d_in[3];   // [D]
    const float* attn = (const float*)d_in[4];   // [H,D,D]
    float* out = (float*)d_out;                  // [B,N,D]

    const size_t smem1 = (size_t)(64 * LDX + 128 * LDX) * sizeof(float);
    const size_t smem2 = 43520;
    cudaFuncSetAttribute(k1_proj, cudaFuncAttributeMaxDynamicSharedMemorySize, (int)smem1);
    cudaFuncSetAttribute(k2_main, cudaFuncAttributeMaxDynamicSharedMemorySize, (int)smem2);

    k1_proj<<<BB * NN / 64, 256, smem1>>>(X, Wk, bias, attn);
    k2_main<<<dim3(NN / 32, BB, 2), 64, smem2>>>(A);
    k3_combine<<<(BB * NN * DD / 4) / 256, 256>>>(X, out);
}